// round 3
// baseline (speedup 1.0000x reference)
#include <cuda_runtime.h>
#include <cstdint>

#define NN  100000
#define EP  1600000
#define ET  3200000
#define FIN 128
#define FH  64
#define FO  32

// ---------------- scratch (static device globals; no allocation) ------------
__device__ int   g_is64;                  // 1 if edge_index buffers are int64
__device__ int   g_deg[NN];
__device__ int   g_rowptr[NN + 1];
__device__ int   g_cursor[NN];
__device__ int   g_src[EP];
__device__ float g_dinv[NN];
__device__ float g_xw[(size_t)NN * FH];   // layer1 linear out, pre-scaled by dinv[row]
__device__ float g_h [(size_t)NN * FH];   // layer1 activation
__device__ float g_hw[(size_t)NN * FO];   // layer2 linear out, pre-scaled by dinv[row]
__device__ float g_z [(size_t)NN * FO];   // layer2 embedding

// read element idx of an edge buffer (logical length 2*EP), honoring dtype flag
__device__ __forceinline__ int edge_at(const void* p, int is64, size_t idx) {
    if (is64) return (int)((const long long*)p)[idx];
    return ((const int*)p)[idx];
}

// ---------------- dtype probe -----------------------------------------------
__global__ void k_detect(const int* __restrict__ p) {
    __shared__ int nz;
    if (threadIdx.x == 0) nz = 0;
    __syncthreads();
    // odd 32-bit words: int64 high-words (always 0) vs int32 payload (~random)
    if (p[threadIdx.x * 2 + 1] != 0) atomicAdd(&nz, 1);
    __syncthreads();
    if (threadIdx.x == 0) g_is64 = (nz == 0) ? 1 : 0;
}

// ---------------- graph preprocessing ---------------------------------------
__global__ void k_zero_deg() {
    int i = blockIdx.x * blockDim.x + threadIdx.x;
    if (i < NN) g_deg[i] = 0;
}

__global__ void k_hist(const void* __restrict__ eidx) {
    int i = blockIdx.x * blockDim.x + threadIdx.x;
    if (i >= EP) return;
    int is64 = g_is64;
    int c = edge_at(eidx, is64, (size_t)EP + i);
    atomicAdd(&g_deg[c], 1);
}

// single-block exclusive scan of g_deg -> g_rowptr / g_cursor (warp-scan based)
__global__ void k_scan() {
    __shared__ int s_wsum[32];
    __shared__ int s_carry;
    __shared__ int s_total;
    int t = threadIdx.x, lane = t & 31, wid = t >> 5;
    if (t == 0) s_carry = 0;
    __syncthreads();
    for (int base = 0; base < NN; base += 1024) {
        int i = base + t;
        int v = (i < NN) ? g_deg[i] : 0;
        int incl = v;
        #pragma unroll
        for (int o = 1; o < 32; o <<= 1) {
            int n = __shfl_up_sync(0xffffffffu, incl, o);
            if (lane >= o) incl += n;
        }
        if (lane == 31) s_wsum[wid] = incl;
        __syncthreads();
        if (t < 32) {
            int ws = s_wsum[t];
            int wi = ws;
            #pragma unroll
            for (int o = 1; o < 32; o <<= 1) {
                int n = __shfl_up_sync(0xffffffffu, wi, o);
                if (lane >= o) wi += n;
            }
            s_wsum[t] = wi - ws;           // exclusive warp offset
            if (t == 31) s_total = wi;     // chunk total
        }
        __syncthreads();
        int excl = s_carry + s_wsum[wid] + incl - v;
        if (i < NN) { g_rowptr[i] = excl; g_cursor[i] = excl; }
        __syncthreads();
        if (t == 0) s_carry += s_total;
        __syncthreads();
    }
    if (t == 0) g_rowptr[NN] = s_carry;
}

__global__ void k_dinv() {
    int i = blockIdx.x * blockDim.x + threadIdx.x;
    if (i < NN) g_dinv[i] = rsqrtf((float)(g_deg[i] + 1));  // +1 self loop
}

__global__ void k_scatter(const void* __restrict__ eidx) {
    int i = blockIdx.x * blockDim.x + threadIdx.x;
    if (i >= EP) return;
    int is64 = g_is64;
    int r = edge_at(eidx, is64, i);               // source
    int c = edge_at(eidx, is64, (size_t)EP + i);  // target
    int p = atomicAdd(&g_cursor[c], 1);
    g_src[p] = r;
}

// ---------------- GEMMs (W fully in SMEM, dinv folded into epilogue) --------
__global__ __launch_bounds__(256) void k_gemm1(const float* __restrict__ x,
                                               const float* __restrict__ W) {
    __shared__ float Ws[FIN * FH];                // 32 KB
    int tx = threadIdx.x, ty = threadIdx.y;       // (8, 32)
    int tid = ty * 8 + tx;
    for (int i = tid; i < FIN * FH; i += 256) Ws[i] = W[i];
    __syncthreads();
    int row = blockIdx.x * 32 + ty;
    const float4* x4 = (const float4*)(x + (size_t)row * FIN);
    float acc[8];
    #pragma unroll
    for (int j = 0; j < 8; j++) acc[j] = 0.f;
    int cb = tx * 8;
    #pragma unroll 4
    for (int k4 = 0; k4 < FIN / 4; k4++) {
        float4 xv = x4[k4];
        const float* w = &Ws[(k4 * 4) * FH + cb];
        #pragma unroll
        for (int j = 0; j < 8; j++) acc[j] += xv.x * w[j];
        #pragma unroll
        for (int j = 0; j < 8; j++) acc[j] += xv.y * w[FH + j];
        #pragma unroll
        for (int j = 0; j < 8; j++) acc[j] += xv.z * w[2 * FH + j];
        #pragma unroll
        for (int j = 0; j < 8; j++) acc[j] += xv.w * w[3 * FH + j];
    }
    float d = g_dinv[row];
    float* o = &g_xw[(size_t)row * FH + cb];
    #pragma unroll
    for (int j = 0; j < 8; j++) o[j] = acc[j] * d;
}

__global__ __launch_bounds__(256) void k_gemm2(const float* __restrict__ W) {
    __shared__ float Ws[FH * FO];                 // 8 KB
    int tx = threadIdx.x, ty = threadIdx.y;       // (8, 32)
    int tid = ty * 8 + tx;
    for (int i = tid; i < FH * FO; i += 256) Ws[i] = W[i];
    __syncthreads();
    int row = blockIdx.x * 32 + ty;
    const float4* h4 = (const float4*)(g_h + (size_t)row * FH);
    float acc[4];
    #pragma unroll
    for (int j = 0; j < 4; j++) acc[j] = 0.f;
    int cb = tx * 4;
    #pragma unroll 4
    for (int k4 = 0; k4 < FH / 4; k4++) {
        float4 hv = h4[k4];
        const float* w = &Ws[(k4 * 4) * FO + cb];
        #pragma unroll
        for (int j = 0; j < 4; j++) acc[j] += hv.x * w[j];
        #pragma unroll
        for (int j = 0; j < 4; j++) acc[j] += hv.y * w[FO + j];
        #pragma unroll
        for (int j = 0; j < 4; j++) acc[j] += hv.z * w[2 * FO + j];
        #pragma unroll
        for (int j = 0; j < 4; j++) acc[j] += hv.w * w[3 * FO + j];
    }
    float d = g_dinv[row];
    float* o = &g_hw[(size_t)row * FO + cb];
    #pragma unroll
    for (int j = 0; j < 4; j++) o[j] = acc[j] * d;
}

// ---------------- aggregation (warp per node, CSR gather) -------------------
__global__ __launch_bounds__(256) void k_agg1(const float* __restrict__ b) {
    int w = (blockIdx.x * 256 + threadIdx.x) >> 5;
    if (w >= NN) return;
    int lane = threadIdx.x & 31;
    const float* base = &g_xw[(size_t)w * FH];
    float a0 = base[lane], a1 = base[lane + 32];   // self-loop term (pre-scaled)
    int s = g_rowptr[w], e = g_rowptr[w + 1];
    int p = s;
    for (; p + 2 <= e; p += 2) {
        int s0 = g_src[p], s1 = g_src[p + 1];
        const float* r0 = &g_xw[(size_t)s0 * FH];
        const float* r1 = &g_xw[(size_t)s1 * FH];
        float v0 = r0[lane], v1 = r0[lane + 32];
        float u0 = r1[lane], u1 = r1[lane + 32];
        a0 += v0 + u0;
        a1 += v1 + u1;
    }
    if (p < e) {
        int s0 = g_src[p];
        a0 += g_xw[(size_t)s0 * FH + lane];
        a1 += g_xw[(size_t)s0 * FH + lane + 32];
    }
    float d = g_dinv[w];
    g_h[(size_t)w * FH + lane]      = fmaxf(fmaf(a0, d, b[lane]),      0.f);
    g_h[(size_t)w * FH + lane + 32] = fmaxf(fmaf(a1, d, b[lane + 32]), 0.f);
}

__global__ __launch_bounds__(256) void k_agg2(const float* __restrict__ b) {
    int w = (blockIdx.x * 256 + threadIdx.x) >> 5;
    if (w >= NN) return;
    int lane = threadIdx.x & 31;
    float a0 = g_hw[(size_t)w * FO + lane];
    int s = g_rowptr[w], e = g_rowptr[w + 1];
    int p = s;
    for (; p + 2 <= e; p += 2) {
        int s0 = g_src[p], s1 = g_src[p + 1];
        float v0 = g_hw[(size_t)s0 * FO + lane];
        float u0 = g_hw[(size_t)s1 * FO + lane];
        a0 += v0 + u0;
    }
    if (p < e) a0 += g_hw[(size_t)g_src[p] * FO + lane];
    float d = g_dinv[w];
    g_z[(size_t)w * FO + lane] = fmaf(a0, d, b[lane]);
}

// ---------------- decode (warp per edge, shuffle reduce) --------------------
__global__ __launch_bounds__(256) void k_decode(const void* __restrict__ pos,
                                                const void* __restrict__ neg,
                                                float* __restrict__ out) {
    int w = (blockIdx.x * 256 + threadIdx.x) >> 5;
    if (w >= ET) return;
    int lane = threadIdx.x & 31;
    int is64 = g_is64;
    int a, bn;
    if (w < EP) {
        a  = edge_at(pos, is64, w);
        bn = edge_at(pos, is64, (size_t)EP + w);
    } else {
        int j = w - EP;
        a  = edge_at(neg, is64, j);
        bn = edge_at(neg, is64, (size_t)EP + j);
    }
    float v = g_z[(size_t)a * FO + lane] * g_z[(size_t)bn * FO + lane];
    #pragma unroll
    for (int o = 16; o; o >>= 1) v += __shfl_xor_sync(0xffffffffu, v, o);
    if (lane == 0) out[w] = v;
}

// edge_index echoed as floats if the harness output includes it
__global__ void k_tail(const void* __restrict__ pos,
                       const void* __restrict__ neg,
                       float* __restrict__ out, int count) {
    int i = blockIdx.x * blockDim.x + threadIdx.x;
    if (i >= count) return;
    int is64 = g_is64;
    int r = i / ET, c = i % ET;
    int v = (c < EP) ? edge_at(pos, is64, (size_t)r * EP + c)
                     : edge_at(neg, is64, (size_t)r * EP + (c - EP));
    out[ET + i] = (float)v;
}

// ---------------- launcher ---------------------------------------------------
extern "C" void kernel_launch(void* const* d_in, const int* in_sizes, int n_in,
                              void* d_out, int out_size) {
    const float *x = 0, *W1 = 0, *b1 = 0, *W2 = 0, *b2 = 0;
    const void *pos = 0, *neg = 0;
    for (int i = 0; i < n_in; i++) {
        switch (in_sizes[i]) {
            case NN * FIN:  x  = (const float*)d_in[i]; break;
            case FIN * FH:  W1 = (const float*)d_in[i]; break;
            case FH:        b1 = (const float*)d_in[i]; break;
            case FH * FO:   W2 = (const float*)d_in[i]; break;
            case FO:        b2 = (const float*)d_in[i]; break;
            case 2 * EP:
                if (!pos) pos = d_in[i];
                else      neg = d_in[i];
                break;
            default: break;
        }
    }
    float* out = (float*)d_out;

    k_detect <<<1, 256>>>((const int*)pos);
    k_zero_deg<<<(NN + 255) / 256, 256>>>();
    k_hist   <<<(EP + 255) / 256, 256>>>(pos);
    k_scan   <<<1, 1024>>>();
    k_dinv   <<<(NN + 255) / 256, 256>>>();
    k_scatter<<<(EP + 255) / 256, 256>>>(pos);

    k_gemm1<<<NN / 32, dim3(8, 32)>>>(x, W1);
    k_agg1 <<<(NN * 32 + 255) / 256, 256>>>(b1);
    k_gemm2<<<NN / 32, dim3(8, 32)>>>(W2);
    k_agg2 <<<(NN * 32 + 255) / 256, 256>>>(b2);

    k_decode<<<((size_t)ET * 32 + 255) / 256, 256>>>(pos, neg, out);

    if (out_size > ET) {
        int cnt = out_size - ET;
        if (cnt > 2 * ET) cnt = 2 * ET;
        k_tail<<<(cnt + 255) / 256, 256>>>(pos, neg, out, cnt);
    }
}

// round 4
// speedup vs baseline: 1.7419x; 1.7419x over previous
#include <cuda_runtime.h>
#include <cstdint>

#define NN  100000
#define EP  1600000
#define ET  3200000
#define FIN 128
#define FH  64
#define FO  32
#define NB  ((NN + 255) / 256)   // 391 scan blocks

// ---------------- scratch (static device globals; no allocation) ------------
__device__ int   g_is64;
__device__ int   g_deg[NN];
__device__ int   g_bsum[512];
__device__ int   g_boff[512];
__device__ int   g_rowptr[NN + 1];
__device__ int   g_cursor[NN];
__device__ int   g_src[EP];
__device__ float g_dinv[NN];
__device__ float g_xw[(size_t)NN * FH];   // layer1 linear out (unscaled)
__device__ float g_h [(size_t)NN * FH];   // layer1 activation
__device__ float g_hw[(size_t)NN * FO];   // layer2 linear out (unscaled)
__device__ float g_z [(size_t)NN * FO];   // layer2 embedding

__device__ __forceinline__ int edge_at(const void* p, int is64, size_t idx) {
    if (is64) return (int)((const long long*)p)[idx];
    return ((const int*)p)[idx];
}

// ---------------- init: zero degrees + dtype probe ---------------------------
__global__ void k_init(const int* __restrict__ p) {
    int i = blockIdx.x * blockDim.x + threadIdx.x;
    if (i < NN) g_deg[i] = 0;
    if (blockIdx.x == 0) {
        __shared__ int nz;
        if (threadIdx.x == 0) nz = 0;
        __syncthreads();
        // odd 32-bit words: int64 high-words (0) vs int32 payload (random ids)
        if (threadIdx.x < 256 && p[threadIdx.x * 2 + 1] != 0) atomicAdd(&nz, 1);
        __syncthreads();
        if (threadIdx.x == 0) g_is64 = (nz == 0) ? 1 : 0;
    }
}

// ---------------- degree histogram ------------------------------------------
__global__ void k_hist(const void* __restrict__ eidx) {
    int i = blockIdx.x * blockDim.x + threadIdx.x;
    if (i >= EP) return;
    int c = edge_at(eidx, g_is64, (size_t)EP + i);
    atomicAdd(&g_deg[c], 1);
}

// ---------------- 3-phase parallel scan --------------------------------------
__global__ __launch_bounds__(256) void k_scanA() {
    int i = blockIdx.x * 256 + threadIdx.x;
    int lane = threadIdx.x & 31, wid = threadIdx.x >> 5;
    __shared__ int sw[8];
    int v = (i < NN) ? g_deg[i] : 0;
    #pragma unroll
    for (int o = 16; o; o >>= 1) v += __shfl_xor_sync(0xffffffffu, v, o);
    if (lane == 0) sw[wid] = v;
    __syncthreads();
    if (threadIdx.x == 0) {
        int t = 0;
        #pragma unroll
        for (int j = 0; j < 8; j++) t += sw[j];
        g_bsum[blockIdx.x] = t;
    }
}

__global__ void k_scanB() {
    __shared__ int sm[16];
    int t = threadIdx.x, lane = t & 31, wid = t >> 5;   // 512 threads
    int v = (t < NB) ? g_bsum[t] : 0;
    int incl = v;
    #pragma unroll
    for (int o = 1; o < 32; o <<= 1) {
        int n = __shfl_up_sync(0xffffffffu, incl, o);
        if (lane >= o) incl += n;
    }
    if (lane == 31) sm[wid] = incl;
    __syncthreads();
    if (t == 0) {
        int run = 0;
        #pragma unroll
        for (int j = 0; j < 16; j++) { int x = sm[j]; sm[j] = run; run += x; }
    }
    __syncthreads();
    int excl = sm[wid] + incl - v;
    if (t < NB) g_boff[t] = excl;
    if (t == NB - 1) g_rowptr[NN] = excl + v;
}

__global__ __launch_bounds__(256) void k_scanC() {
    int i = blockIdx.x * 256 + threadIdx.x;
    int lane = threadIdx.x & 31, wid = threadIdx.x >> 5;
    __shared__ int sw[8];
    int v = (i < NN) ? g_deg[i] : 0;
    int incl = v;
    #pragma unroll
    for (int o = 1; o < 32; o <<= 1) {
        int n = __shfl_up_sync(0xffffffffu, incl, o);
        if (lane >= o) incl += n;
    }
    if (lane == 31) sw[wid] = incl;
    __syncthreads();
    if (threadIdx.x == 0) {
        int run = 0;
        #pragma unroll
        for (int j = 0; j < 8; j++) { int x = sw[j]; sw[j] = run; run += x; }
    }
    __syncthreads();
    int excl = g_boff[blockIdx.x] + sw[wid] + incl - v;
    if (i < NN) {
        g_rowptr[i] = excl;
        g_cursor[i] = excl;
        g_dinv[i]   = rsqrtf((float)(v + 1));   // +1 self loop
    }
}

// ---------------- CSR scatter ------------------------------------------------
__global__ void k_scatter(const void* __restrict__ eidx) {
    int i = blockIdx.x * blockDim.x + threadIdx.x;
    if (i >= EP) return;
    int is64 = g_is64;
    int r = edge_at(eidx, is64, i);
    int c = edge_at(eidx, is64, (size_t)EP + i);
    int p = atomicAdd(&g_cursor[c], 1);
    g_src[p] = r;
}

// ---------------- GEMMs (W in SMEM, no dinv dependence) ----------------------
__global__ __launch_bounds__(256) void k_gemm1(const float* __restrict__ x,
                                               const float* __restrict__ W) {
    __shared__ float Ws[FIN * FH];
    int tx = threadIdx.x, ty = threadIdx.y;       // (8, 32)
    int tid = ty * 8 + tx;
    for (int i = tid; i < FIN * FH; i += 256) Ws[i] = W[i];
    __syncthreads();
    int row = blockIdx.x * 32 + ty;
    const float4* x4 = (const float4*)(x + (size_t)row * FIN);
    float acc[8];
    #pragma unroll
    for (int j = 0; j < 8; j++) acc[j] = 0.f;
    int cb = tx * 8;
    #pragma unroll 4
    for (int k4 = 0; k4 < FIN / 4; k4++) {
        float4 xv = x4[k4];
        const float* w = &Ws[(k4 * 4) * FH + cb];
        #pragma unroll
        for (int j = 0; j < 8; j++) acc[j] = fmaf(xv.x, w[j],          acc[j]);
        #pragma unroll
        for (int j = 0; j < 8; j++) acc[j] = fmaf(xv.y, w[FH + j],     acc[j]);
        #pragma unroll
        for (int j = 0; j < 8; j++) acc[j] = fmaf(xv.z, w[2 * FH + j], acc[j]);
        #pragma unroll
        for (int j = 0; j < 8; j++) acc[j] = fmaf(xv.w, w[3 * FH + j], acc[j]);
    }
    float* o = &g_xw[(size_t)row * FH + cb];
    #pragma unroll
    for (int j = 0; j < 8; j++) o[j] = acc[j];
}

__global__ __launch_bounds__(256) void k_gemm2(const float* __restrict__ W) {
    __shared__ float Ws[FH * FO];
    int tx = threadIdx.x, ty = threadIdx.y;       // (8, 32)
    int tid = ty * 8 + tx;
    for (int i = tid; i < FH * FO; i += 256) Ws[i] = W[i];
    __syncthreads();
    int row = blockIdx.x * 32 + ty;
    const float4* h4 = (const float4*)(g_h + (size_t)row * FH);
    float acc[4];
    #pragma unroll
    for (int j = 0; j < 4; j++) acc[j] = 0.f;
    int cb = tx * 4;
    #pragma unroll 4
    for (int k4 = 0; k4 < FH / 4; k4++) {
        float4 hv = h4[k4];
        const float* w = &Ws[(k4 * 4) * FO + cb];
        #pragma unroll
        for (int j = 0; j < 4; j++) acc[j] = fmaf(hv.x, w[j],          acc[j]);
        #pragma unroll
        for (int j = 0; j < 4; j++) acc[j] = fmaf(hv.y, w[FO + j],     acc[j]);
        #pragma unroll
        for (int j = 0; j < 4; j++) acc[j] = fmaf(hv.z, w[2 * FO + j], acc[j]);
        #pragma unroll
        for (int j = 0; j < 4; j++) acc[j] = fmaf(hv.w, w[3 * FO + j], acc[j]);
    }
    float* o = &g_hw[(size_t)row * FO + cb];
    #pragma unroll
    for (int j = 0; j < 4; j++) o[j] = acc[j];
}

// ---------------- aggregation (warp per node, dinv[src] folded in) ----------
__global__ __launch_bounds__(256) void k_agg1(const float* __restrict__ b) {
    int w = (blockIdx.x * 256 + threadIdx.x) >> 5;
    if (w >= NN) return;
    int lane = threadIdx.x & 31;
    float dw = g_dinv[w];
    const float* base = &g_xw[(size_t)w * FH];
    float a0 = base[lane] * dw, a1 = base[lane + 32] * dw;  // self loop
    int s = g_rowptr[w], e = g_rowptr[w + 1];
    int p = s;
    for (; p + 4 <= e; p += 4) {
        int s0 = g_src[p], s1 = g_src[p + 1], s2 = g_src[p + 2], s3 = g_src[p + 3];
        float d0 = g_dinv[s0], d1 = g_dinv[s1], d2 = g_dinv[s2], d3 = g_dinv[s3];
        const float* r0 = &g_xw[(size_t)s0 * FH];
        const float* r1 = &g_xw[(size_t)s1 * FH];
        const float* r2 = &g_xw[(size_t)s2 * FH];
        const float* r3 = &g_xw[(size_t)s3 * FH];
        float v00 = r0[lane], v01 = r0[lane + 32];
        float v10 = r1[lane], v11 = r1[lane + 32];
        float v20 = r2[lane], v21 = r2[lane + 32];
        float v30 = r3[lane], v31 = r3[lane + 32];
        a0 = fmaf(v00, d0, a0); a1 = fmaf(v01, d0, a1);
        a0 = fmaf(v10, d1, a0); a1 = fmaf(v11, d1, a1);
        a0 = fmaf(v20, d2, a0); a1 = fmaf(v21, d2, a1);
        a0 = fmaf(v30, d3, a0); a1 = fmaf(v31, d3, a1);
    }
    for (; p < e; p++) {
        int s0 = g_src[p];
        float d0 = g_dinv[s0];
        a0 = fmaf(g_xw[(size_t)s0 * FH + lane],      d0, a0);
        a1 = fmaf(g_xw[(size_t)s0 * FH + lane + 32], d0, a1);
    }
    g_h[(size_t)w * FH + lane]      = fmaxf(fmaf(a0, dw, b[lane]),      0.f);
    g_h[(size_t)w * FH + lane + 32] = fmaxf(fmaf(a1, dw, b[lane + 32]), 0.f);
}

__global__ __launch_bounds__(256) void k_agg2(const float* __restrict__ b) {
    int w = (blockIdx.x * 256 + threadIdx.x) >> 5;
    if (w >= NN) return;
    int lane = threadIdx.x & 31;
    float dw = g_dinv[w];
    float a0 = g_hw[(size_t)w * FO + lane] * dw;    // self loop
    int s = g_rowptr[w], e = g_rowptr[w + 1];
    int p = s;
    for (; p + 4 <= e; p += 4) {
        int s0 = g_src[p], s1 = g_src[p + 1], s2 = g_src[p + 2], s3 = g_src[p + 3];
        float d0 = g_dinv[s0], d1 = g_dinv[s1], d2 = g_dinv[s2], d3 = g_dinv[s3];
        float v0 = g_hw[(size_t)s0 * FO + lane];
        float v1 = g_hw[(size_t)s1 * FO + lane];
        float v2 = g_hw[(size_t)s2 * FO + lane];
        float v3 = g_hw[(size_t)s3 * FO + lane];
        a0 = fmaf(v0, d0, a0);
        a0 = fmaf(v1, d1, a0);
        a0 = fmaf(v2, d2, a0);
        a0 = fmaf(v3, d3, a0);
    }
    for (; p < e; p++) {
        int s0 = g_src[p];
        a0 = fmaf(g_hw[(size_t)s0 * FO + lane], g_dinv[s0], a0);
    }
    g_z[(size_t)w * FO + lane] = fmaf(a0, dw, b[lane]);
}

// ---------------- decode: 8 lanes/edge, 4 edges/warp, float4 loads ----------
__global__ __launch_bounds__(256) void k_decode(const void* __restrict__ pos,
                                                const void* __restrict__ neg,
                                                float* __restrict__ out) {
    int warp = (blockIdx.x * 256 + threadIdx.x) >> 5;
    int lane = threadIdx.x & 31;
    int sub = lane >> 3, l8 = lane & 7;
    size_t e = (size_t)warp * 4 + sub;               // grid sized exactly
    int is64 = g_is64;
    int a, bn;
    if (e < EP) {
        a  = edge_at(pos, is64, e);
        bn = edge_at(pos, is64, (size_t)EP + e);
    } else {
        size_t j = e - EP;
        a  = edge_at(neg, is64, j);
        bn = edge_at(neg, is64, (size_t)EP + j);
    }
    float4 va = ((const float4*)(g_z + (size_t)a  * FO))[l8];
    float4 vb = ((const float4*)(g_z + (size_t)bn * FO))[l8];
    float v = va.x * vb.x + va.y * vb.y + va.z * vb.z + va.w * vb.w;
    v += __shfl_xor_sync(0xffffffffu, v, 4);
    v += __shfl_xor_sync(0xffffffffu, v, 2);
    v += __shfl_xor_sync(0xffffffffu, v, 1);
    if (l8 == 0) out[e] = v;
}

// edge_index echoed as floats if the harness output includes it
__global__ void k_tail(const void* __restrict__ pos,
                       const void* __restrict__ neg,
                       float* __restrict__ out, int count) {
    int i = blockIdx.x * blockDim.x + threadIdx.x;
    if (i >= count) return;
    int is64 = g_is64;
    int r = i / ET, c = i % ET;
    int v = (c < EP) ? edge_at(pos, is64, (size_t)r * EP + c)
                     : edge_at(neg, is64, (size_t)r * EP + (c - EP));
    out[ET + i] = (float)v;
}

// ---------------- launcher ---------------------------------------------------
extern "C" void kernel_launch(void* const* d_in, const int* in_sizes, int n_in,
                              void* d_out, int out_size) {
    // created on the first (uncaptured) correctness call; reused under capture
    static cudaStream_t s2 = 0;
    static cudaEvent_t evFork = 0, evJoin = 0;
    if (!s2) {
        cudaStreamCreateWithFlags(&s2, cudaStreamNonBlocking);
        cudaEventCreateWithFlags(&evFork, cudaEventDisableTiming);
        cudaEventCreateWithFlags(&evJoin, cudaEventDisableTiming);
    }

    const float *x = 0, *W1 = 0, *b1 = 0, *W2 = 0, *b2 = 0;
    const void *pos = 0, *neg = 0;
    for (int i = 0; i < n_in; i++) {
        switch (in_sizes[i]) {
            case NN * FIN:  x  = (const float*)d_in[i]; break;
            case FIN * FH:  W1 = (const float*)d_in[i]; break;
            case FH:        b1 = (const float*)d_in[i]; break;
            case FH * FO:   W2 = (const float*)d_in[i]; break;
            case FO:        b2 = (const float*)d_in[i]; break;
            case 2 * EP:
                if (!pos) pos = d_in[i];
                else      neg = d_in[i];
                break;
            default: break;
        }
    }
    float* out = (float*)d_out;

    // fork: GEMM1 (independent of graph preprocessing) on side stream
    cudaEventRecord(evFork, 0);
    cudaStreamWaitEvent(s2, evFork, 0);
    k_gemm1<<<NN / 32, dim3(8, 32), 0, s2>>>(x, W1);
    cudaEventRecord(evJoin, s2);

    // preprocessing chain on main stream
    k_init   <<<(NN + 255) / 256, 256>>>((const int*)pos);
    k_hist   <<<(EP + 255) / 256, 256>>>(pos);
    k_scanA  <<<NB, 256>>>();
    k_scanB  <<<1, 512>>>();
    k_scanC  <<<NB, 256>>>();
    k_scatter<<<(EP + 255) / 256, 256>>>(pos);

    // join, then layer pipeline
    cudaStreamWaitEvent(0, evJoin, 0);
    k_agg1 <<<(NN * 32 + 255) / 256, 256>>>(b1);
    k_gemm2<<<NN / 32, dim3(8, 32)>>>(W2);
    k_agg2 <<<(NN * 32 + 255) / 256, 256>>>(b2);

    // decode: ET/4 edges per warp-group of 4; grid exact (ET % 32 == 0)
    k_decode<<<(ET / 4) * 32 / 256, 256>>>(pos, neg, out);

    if (out_size > ET) {
        int cnt = out_size - ET;
        if (cnt > 2 * ET) cnt = 2 * ET;
        k_tail<<<(cnt + 255) / 256, 256>>>(pos, neg, out, cnt);
    }
}

// round 5
// speedup vs baseline: 1.7925x; 1.0291x over previous
#include <cuda_runtime.h>
#include <cstdint>

#define NN  100000
#define EP  1600000
#define ET  3200000
#define FIN 128
#define FH  64
#define FO  32
#define NB  ((NN + 255) / 256)   // 391 scan blocks

// ---------------- scratch (static device globals; no allocation) ------------
__device__ int   g_is64;
__device__ int   g_deg[NN];
__device__ int   g_bsum[512];
__device__ int   g_boff[512];
__device__ int   g_rowptr[NN + 1];
__device__ int   g_cursor[NN];
__device__ uint2 g_edge[EP];              // {src, __float_as_uint(dinv[src])}
__device__ float g_dinv[NN];
__device__ float g_xw[(size_t)NN * FH];   // layer1 linear out (unscaled)
__device__ float g_h [(size_t)NN * FH];   // layer1 activation
__device__ float g_hw[(size_t)NN * FO];   // layer2 linear out (unscaled)
__device__ float g_z [(size_t)NN * FO];   // layer2 embedding

__device__ __forceinline__ int edge_at(const void* p, int is64, size_t idx) {
    if (is64) return (int)((const long long*)p)[idx];
    return ((const int*)p)[idx];
}

// ---------------- init: zero degrees + dtype probe ---------------------------
__global__ void k_init(const int* __restrict__ p) {
    int i = blockIdx.x * blockDim.x + threadIdx.x;
    if (i < NN) g_deg[i] = 0;
    if (blockIdx.x == 0) {
        __shared__ int nz;
        if (threadIdx.x == 0) nz = 0;
        __syncthreads();
        // odd 32-bit words: int64 high-words (0) vs int32 payload (random ids)
        if (threadIdx.x < 256 && p[threadIdx.x * 2 + 1] != 0) atomicAdd(&nz, 1);
        __syncthreads();
        if (threadIdx.x == 0) g_is64 = (nz == 0) ? 1 : 0;
    }
}

// ---------------- degree histogram (2 edges / thread) ------------------------
__global__ void k_hist(const void* __restrict__ eidx) {
    int i = blockIdx.x * blockDim.x + threadIdx.x;   // pair index
    if (i * 2 >= EP) return;
    int c0, c1;
    if (g_is64) {
        longlong2 v = ((const longlong2*)((const long long*)eidx + EP))[i];
        c0 = (int)v.x; c1 = (int)v.y;
    } else {
        int2 v = ((const int2*)((const int*)eidx + EP))[i];
        c0 = v.x; c1 = v.y;
    }
    atomicAdd(&g_deg[c0], 1);
    atomicAdd(&g_deg[c1], 1);
}

// ---------------- 3-phase parallel scan --------------------------------------
__global__ __launch_bounds__(256) void k_scanA() {
    int i = blockIdx.x * 256 + threadIdx.x;
    int lane = threadIdx.x & 31, wid = threadIdx.x >> 5;
    __shared__ int sw[8];
    int v = (i < NN) ? g_deg[i] : 0;
    #pragma unroll
    for (int o = 16; o; o >>= 1) v += __shfl_xor_sync(0xffffffffu, v, o);
    if (lane == 0) sw[wid] = v;
    __syncthreads();
    if (threadIdx.x == 0) {
        int t = 0;
        #pragma unroll
        for (int j = 0; j < 8; j++) t += sw[j];
        g_bsum[blockIdx.x] = t;
    }
}

__global__ void k_scanB() {
    __shared__ int sm[16];
    int t = threadIdx.x, lane = t & 31, wid = t >> 5;   // 512 threads
    int v = (t < NB) ? g_bsum[t] : 0;
    int incl = v;
    #pragma unroll
    for (int o = 1; o < 32; o <<= 1) {
        int n = __shfl_up_sync(0xffffffffu, incl, o);
        if (lane >= o) incl += n;
    }
    if (lane == 31) sm[wid] = incl;
    __syncthreads();
    if (t == 0) {
        int run = 0;
        #pragma unroll
        for (int j = 0; j < 16; j++) { int x = sm[j]; sm[j] = run; run += x; }
    }
    __syncthreads();
    int excl = sm[wid] + incl - v;
    if (t < NB) g_boff[t] = excl;
    if (t == NB - 1) g_rowptr[NN] = excl + v;
}

__global__ __launch_bounds__(256) void k_scanC() {
    int i = blockIdx.x * 256 + threadIdx.x;
    int lane = threadIdx.x & 31, wid = threadIdx.x >> 5;
    __shared__ int sw[8];
    int v = (i < NN) ? g_deg[i] : 0;
    int incl = v;
    #pragma unroll
    for (int o = 1; o < 32; o <<= 1) {
        int n = __shfl_up_sync(0xffffffffu, incl, o);
        if (lane >= o) incl += n;
    }
    if (lane == 31) sw[wid] = incl;
    __syncthreads();
    if (threadIdx.x == 0) {
        int run = 0;
        #pragma unroll
        for (int j = 0; j < 8; j++) { int x = sw[j]; sw[j] = run; run += x; }
    }
    __syncthreads();
    int excl = g_boff[blockIdx.x] + sw[wid] + incl - v;
    if (i < NN) {
        g_rowptr[i] = excl;
        g_cursor[i] = excl;
        g_dinv[i]   = rsqrtf((float)(v + 1));   // +1 self loop
    }
}

// ---------------- CSR scatter: pack {src, dinv[src]} (2 edges / thread) ------
__global__ void k_scatter(const void* __restrict__ eidx) {
    int i = blockIdx.x * blockDim.x + threadIdx.x;   // pair index
    if (i * 2 >= EP) return;
    int r0, r1, c0, c1;
    if (g_is64) {
        const long long* e64 = (const long long*)eidx;
        longlong2 vr = ((const longlong2*)e64)[i];
        longlong2 vc = ((const longlong2*)(e64 + EP))[i];
        r0 = (int)vr.x; r1 = (int)vr.y;
        c0 = (int)vc.x; c1 = (int)vc.y;
    } else {
        const int* e32 = (const int*)eidx;
        int2 vr = ((const int2*)e32)[i];
        int2 vc = ((const int2*)(e32 + EP))[i];
        r0 = vr.x; r1 = vr.y;
        c0 = vc.x; c1 = vc.y;
    }
    float d0 = g_dinv[r0], d1 = g_dinv[r1];
    int p0 = atomicAdd(&g_cursor[c0], 1);
    g_edge[p0] = make_uint2((unsigned)r0, __float_as_uint(d0));
    int p1 = atomicAdd(&g_cursor[c1], 1);
    g_edge[p1] = make_uint2((unsigned)r1, __float_as_uint(d1));
}

// ---------------- GEMMs (W in SMEM, no dinv dependence) ----------------------
__global__ __launch_bounds__(256) void k_gemm1(const float* __restrict__ x,
                                               const float* __restrict__ W) {
    __shared__ float Ws[FIN * FH];
    int tx = threadIdx.x, ty = threadIdx.y;       // (8, 32)
    int tid = ty * 8 + tx;
    for (int i = tid; i < FIN * FH; i += 256) Ws[i] = W[i];
    __syncthreads();
    int row = blockIdx.x * 32 + ty;
    const float4* x4 = (const float4*)(x + (size_t)row * FIN);
    float acc[8];
    #pragma unroll
    for (int j = 0; j < 8; j++) acc[j] = 0.f;
    int cb = tx * 8;
    #pragma unroll 4
    for (int k4 = 0; k4 < FIN / 4; k4++) {
        float4 xv = x4[k4];
        const float* w = &Ws[(k4 * 4) * FH + cb];
        #pragma unroll
        for (int j = 0; j < 8; j++) acc[j] = fmaf(xv.x, w[j],          acc[j]);
        #pragma unroll
        for (int j = 0; j < 8; j++) acc[j] = fmaf(xv.y, w[FH + j],     acc[j]);
        #pragma unroll
        for (int j = 0; j < 8; j++) acc[j] = fmaf(xv.z, w[2 * FH + j], acc[j]);
        #pragma unroll
        for (int j = 0; j < 8; j++) acc[j] = fmaf(xv.w, w[3 * FH + j], acc[j]);
    }
    float* o = &g_xw[(size_t)row * FH + cb];
    #pragma unroll
    for (int j = 0; j < 8; j++) o[j] = acc[j];
}

__global__ __launch_bounds__(256) void k_gemm2(const float* __restrict__ W) {
    __shared__ float Ws[FH * FO];
    int tx = threadIdx.x, ty = threadIdx.y;       // (8, 32)
    int tid = ty * 8 + tx;
    for (int i = tid; i < FH * FO; i += 256) Ws[i] = W[i];
    __syncthreads();
    int row = blockIdx.x * 32 + ty;
    const float4* h4 = (const float4*)(g_h + (size_t)row * FH);
    float acc[4];
    #pragma unroll
    for (int j = 0; j < 4; j++) acc[j] = 0.f;
    int cb = tx * 4;
    #pragma unroll 4
    for (int k4 = 0; k4 < FH / 4; k4++) {
        float4 hv = h4[k4];
        const float* w = &Ws[(k4 * 4) * FO + cb];
        #pragma unroll
        for (int j = 0; j < 4; j++) acc[j] = fmaf(hv.x, w[j],          acc[j]);
        #pragma unroll
        for (int j = 0; j < 4; j++) acc[j] = fmaf(hv.y, w[FO + j],     acc[j]);
        #pragma unroll
        for (int j = 0; j < 4; j++) acc[j] = fmaf(hv.z, w[2 * FO + j], acc[j]);
        #pragma unroll
        for (int j = 0; j < 4; j++) acc[j] = fmaf(hv.w, w[3 * FO + j], acc[j]);
    }
    float* o = &g_hw[(size_t)row * FO + cb];
    #pragma unroll
    for (int j = 0; j < 4; j++) o[j] = acc[j];
}

// ---------------- aggregation (warp per node, packed edge records) ----------
__global__ __launch_bounds__(256) void k_agg1(const float* __restrict__ b) {
    int w = (blockIdx.x * 256 + threadIdx.x) >> 5;
    if (w >= NN) return;
    int lane = threadIdx.x & 31;
    float dw = g_dinv[w];
    const float* base = &g_xw[(size_t)w * FH];
    float a0 = base[lane] * dw, a1 = base[lane + 32] * dw;  // self loop
    int s = g_rowptr[w], e = g_rowptr[w + 1];
    int p = s;
    for (; p + 4 <= e; p += 4) {
        uint2 e0 = g_edge[p],     e1 = g_edge[p + 1];
        uint2 e2 = g_edge[p + 2], e3 = g_edge[p + 3];
        const float* r0 = &g_xw[(size_t)e0.x * FH];
        const float* r1 = &g_xw[(size_t)e1.x * FH];
        const float* r2 = &g_xw[(size_t)e2.x * FH];
        const float* r3 = &g_xw[(size_t)e3.x * FH];
        float v00 = r0[lane], v01 = r0[lane + 32];
        float v10 = r1[lane], v11 = r1[lane + 32];
        float v20 = r2[lane], v21 = r2[lane + 32];
        float v30 = r3[lane], v31 = r3[lane + 32];
        float d0 = __uint_as_float(e0.y), d1 = __uint_as_float(e1.y);
        float d2 = __uint_as_float(e2.y), d3 = __uint_as_float(e3.y);
        a0 = fmaf(v00, d0, a0); a1 = fmaf(v01, d0, a1);
        a0 = fmaf(v10, d1, a0); a1 = fmaf(v11, d1, a1);
        a0 = fmaf(v20, d2, a0); a1 = fmaf(v21, d2, a1);
        a0 = fmaf(v30, d3, a0); a1 = fmaf(v31, d3, a1);
    }
    for (; p < e; p++) {
        uint2 e0 = g_edge[p];
        float d0 = __uint_as_float(e0.y);
        a0 = fmaf(g_xw[(size_t)e0.x * FH + lane],      d0, a0);
        a1 = fmaf(g_xw[(size_t)e0.x * FH + lane + 32], d0, a1);
    }
    g_h[(size_t)w * FH + lane]      = fmaxf(fmaf(a0, dw, b[lane]),      0.f);
    g_h[(size_t)w * FH + lane + 32] = fmaxf(fmaf(a1, dw, b[lane + 32]), 0.f);
}

__global__ __launch_bounds__(256) void k_agg2(const float* __restrict__ b) {
    int w = (blockIdx.x * 256 + threadIdx.x) >> 5;
    if (w >= NN) return;
    int lane = threadIdx.x & 31;
    float dw = g_dinv[w];
    float a0 = g_hw[(size_t)w * FO + lane] * dw;    // self loop
    int s = g_rowptr[w], e = g_rowptr[w + 1];
    int p = s;
    for (; p + 4 <= e; p += 4) {
        uint2 e0 = g_edge[p],     e1 = g_edge[p + 1];
        uint2 e2 = g_edge[p + 2], e3 = g_edge[p + 3];
        float v0 = g_hw[(size_t)e0.x * FO + lane];
        float v1 = g_hw[(size_t)e1.x * FO + lane];
        float v2 = g_hw[(size_t)e2.x * FO + lane];
        float v3 = g_hw[(size_t)e3.x * FO + lane];
        a0 = fmaf(v0, __uint_as_float(e0.y), a0);
        a0 = fmaf(v1, __uint_as_float(e1.y), a0);
        a0 = fmaf(v2, __uint_as_float(e2.y), a0);
        a0 = fmaf(v3, __uint_as_float(e3.y), a0);
    }
    for (; p < e; p++) {
        uint2 e0 = g_edge[p];
        a0 = fmaf(g_hw[(size_t)e0.x * FO + lane], __uint_as_float(e0.y), a0);
    }
    g_z[(size_t)w * FO + lane] = fmaf(a0, dw, b[lane]);
}

// ---------------- decode: 8 edges/warp, 8 lanes/edge, float4 loads ----------
__global__ __launch_bounds__(256) void k_decode(const void* __restrict__ pos,
                                                const void* __restrict__ neg,
                                                float* __restrict__ out) {
    int warp = (blockIdx.x * 256 + threadIdx.x) >> 5;
    int lane = threadIdx.x & 31;
    int sub = lane >> 3, l8 = lane & 7;
    size_t e0 = (size_t)warp * 8 + sub * 2;          // ET % 8 == 0, grid exact
    size_t e1 = e0 + 1;
    int is64 = g_is64;
    int a0, b0, a1, b1;
    if (e1 < EP) {
        a0 = edge_at(pos, is64, e0);  b0 = edge_at(pos, is64, (size_t)EP + e0);
        a1 = edge_at(pos, is64, e1);  b1 = edge_at(pos, is64, (size_t)EP + e1);
    } else if (e0 >= EP) {
        size_t j0 = e0 - EP, j1 = e1 - EP;
        a0 = edge_at(neg, is64, j0);  b0 = edge_at(neg, is64, (size_t)EP + j0);
        a1 = edge_at(neg, is64, j1);  b1 = edge_at(neg, is64, (size_t)EP + j1);
    } else {                                          // straddle (one warp)
        a0 = edge_at(pos, is64, e0);  b0 = edge_at(pos, is64, (size_t)EP + e0);
        a1 = edge_at(neg, is64, 0);   b1 = edge_at(neg, is64, EP);
    }
    float4 va0 = ((const float4*)(g_z + (size_t)a0 * FO))[l8];
    float4 vb0 = ((const float4*)(g_z + (size_t)b0 * FO))[l8];
    float4 va1 = ((const float4*)(g_z + (size_t)a1 * FO))[l8];
    float4 vb1 = ((const float4*)(g_z + (size_t)b1 * FO))[l8];
    float v0 = va0.x * vb0.x + va0.y * vb0.y + va0.z * vb0.z + va0.w * vb0.w;
    float v1 = va1.x * vb1.x + va1.y * vb1.y + va1.z * vb1.z + va1.w * vb1.w;
    v0 += __shfl_xor_sync(0xffffffffu, v0, 4);
    v1 += __shfl_xor_sync(0xffffffffu, v1, 4);
    v0 += __shfl_xor_sync(0xffffffffu, v0, 2);
    v1 += __shfl_xor_sync(0xffffffffu, v1, 2);
    v0 += __shfl_xor_sync(0xffffffffu, v0, 1);
    v1 += __shfl_xor_sync(0xffffffffu, v1, 1);
    if (l8 == 0) { out[e0] = v0; out[e1] = v1; }
}

// edge_index echoed as floats if the harness output includes it
__global__ void k_tail(const void* __restrict__ pos,
                       const void* __restrict__ neg,
                       float* __restrict__ out, int count) {
    int i = blockIdx.x * blockDim.x + threadIdx.x;
    if (i >= count) return;
    int is64 = g_is64;
    int r = i / ET, c = i % ET;
    int v = (c < EP) ? edge_at(pos, is64, (size_t)r * EP + c)
                     : edge_at(neg, is64, (size_t)r * EP + (c - EP));
    out[ET + i] = (float)v;
}

// ---------------- launcher ---------------------------------------------------
extern "C" void kernel_launch(void* const* d_in, const int* in_sizes, int n_in,
                              void* d_out, int out_size) {
    // created on the first (uncaptured) correctness call; reused under capture
    static cudaStream_t s2 = 0;
    static cudaEvent_t evFork = 0, evJoin = 0;
    if (!s2) {
        cudaStreamCreateWithFlags(&s2, cudaStreamNonBlocking);
        cudaEventCreateWithFlags(&evFork, cudaEventDisableTiming);
        cudaEventCreateWithFlags(&evJoin, cudaEventDisableTiming);
    }

    const float *x = 0, *W1 = 0, *b1 = 0, *W2 = 0, *b2 = 0;
    const void *pos = 0, *neg = 0;
    for (int i = 0; i < n_in; i++) {
        switch (in_sizes[i]) {
            case NN * FIN:  x  = (const float*)d_in[i]; break;
            case FIN * FH:  W1 = (const float*)d_in[i]; break;
            case FH:        b1 = (const float*)d_in[i]; break;
            case FH * FO:   W2 = (const float*)d_in[i]; break;
            case FO:        b2 = (const float*)d_in[i]; break;
            case 2 * EP:
                if (!pos) pos = d_in[i];
                else      neg = d_in[i];
                break;
            default: break;
        }
    }
    float* out = (float*)d_out;

    // fork: GEMM1 (independent of graph preprocessing) on side stream
    cudaEventRecord(evFork, 0);
    cudaStreamWaitEvent(s2, evFork, 0);
    k_gemm1<<<NN / 32, dim3(8, 32), 0, s2>>>(x, W1);
    cudaEventRecord(evJoin, s2);

    // preprocessing chain on main stream
    k_init   <<<(NN + 255) / 256, 256>>>((const int*)pos);
    k_hist   <<<(EP / 2 + 255) / 256, 256>>>(pos);
    k_scanA  <<<NB, 256>>>();
    k_scanB  <<<1, 512>>>();
    k_scanC  <<<NB, 256>>>();
    k_scatter<<<(EP / 2 + 255) / 256, 256>>>(pos);

    // join, then layer pipeline
    cudaStreamWaitEvent(0, evJoin, 0);
    k_agg1 <<<(NN * 32 + 255) / 256, 256>>>(b1);
    k_gemm2<<<NN / 32, dim3(8, 32)>>>(W2);
    k_agg2 <<<(NN * 32 + 255) / 256, 256>>>(b2);

    // decode: 8 edges per warp; grid exact (ET % 8 == 0)
    k_decode<<<(ET / 8) * 32 / 256, 256>>>(pos, neg, out);

    if (out_size > ET) {
        int cnt = out_size - ET;
        if (cnt > 2 * ET) cnt = 2 * ET;
        k_tail<<<(cnt + 255) / 256, 256>>>(pos, neg, out, cnt);
    }
}

// round 6
// speedup vs baseline: 1.8104x; 1.0100x over previous
#include <cuda_runtime.h>
#include <cstdint>

#define NN  100000
#define EP  1600000
#define ET  3200000
#define FIN 128
#define FH  64
#define FO  32
#define NB  ((NN + 255) / 256)   // 391 scan blocks

// ---------------- scratch (static device globals; no allocation) ------------
__device__ int   g_is64;
__device__ int   g_deg[NN];
__device__ int   g_bsum[512];
__device__ int   g_boff[512];
__device__ int   g_rowptr[NN + 1];
__device__ int   g_cursor[NN];
__device__ uint2 g_edge[EP];              // {src, __float_as_uint(dinv[src])}
__device__ float g_dinv[NN];
__device__ float g_xw[(size_t)NN * FH];   // layer1 linear out (unscaled)
__device__ float g_hw[(size_t)NN * FO];   // layer2 linear out (unscaled)
__device__ float g_z [(size_t)NN * FO];   // layer2 embedding

__device__ __forceinline__ int edge_at(const void* p, int is64, size_t idx) {
    if (is64) return (int)((const long long*)p)[idx];
    return ((const int*)p)[idx];
}

// ---------------- init: zero degrees + dtype probe ---------------------------
__global__ void k_init(const int* __restrict__ p) {
    int i = blockIdx.x * blockDim.x + threadIdx.x;
    if (i < NN) g_deg[i] = 0;
    if (blockIdx.x == 0) {
        __shared__ int nz;
        if (threadIdx.x == 0) nz = 0;
        __syncthreads();
        // odd 32-bit words: int64 high-words (0) vs int32 payload (random ids)
        if (threadIdx.x < 256 && p[threadIdx.x * 2 + 1] != 0) atomicAdd(&nz, 1);
        __syncthreads();
        if (threadIdx.x == 0) g_is64 = (nz == 0) ? 1 : 0;
    }
}

// ---------------- degree histogram (2 edges / thread) ------------------------
__global__ void k_hist(const void* __restrict__ eidx) {
    int i = blockIdx.x * blockDim.x + threadIdx.x;   // pair index
    if (i * 2 >= EP) return;
    int c0, c1;
    if (g_is64) {
        longlong2 v = ((const longlong2*)((const long long*)eidx + EP))[i];
        c0 = (int)v.x; c1 = (int)v.y;
    } else {
        int2 v = ((const int2*)((const int*)eidx + EP))[i];
        c0 = v.x; c1 = v.y;
    }
    atomicAdd(&g_deg[c0], 1);
    atomicAdd(&g_deg[c1], 1);
}

// ---------------- 3-phase parallel scan --------------------------------------
__global__ __launch_bounds__(256) void k_scanA() {
    int i = blockIdx.x * 256 + threadIdx.x;
    int lane = threadIdx.x & 31, wid = threadIdx.x >> 5;
    __shared__ int sw[8];
    int v = (i < NN) ? g_deg[i] : 0;
    #pragma unroll
    for (int o = 16; o; o >>= 1) v += __shfl_xor_sync(0xffffffffu, v, o);
    if (lane == 0) sw[wid] = v;
    __syncthreads();
    if (threadIdx.x == 0) {
        int t = 0;
        #pragma unroll
        for (int j = 0; j < 8; j++) t += sw[j];
        g_bsum[blockIdx.x] = t;
    }
}

__global__ void k_scanB() {
    __shared__ int sm[16];
    int t = threadIdx.x, lane = t & 31, wid = t >> 5;   // 512 threads
    int v = (t < NB) ? g_bsum[t] : 0;
    int incl = v;
    #pragma unroll
    for (int o = 1; o < 32; o <<= 1) {
        int n = __shfl_up_sync(0xffffffffu, incl, o);
        if (lane >= o) incl += n;
    }
    if (lane == 31) sm[wid] = incl;
    __syncthreads();
    if (t == 0) {
        int run = 0;
        #pragma unroll
        for (int j = 0; j < 16; j++) { int x = sm[j]; sm[j] = run; run += x; }
    }
    __syncthreads();
    int excl = sm[wid] + incl - v;
    if (t < NB) g_boff[t] = excl;
    if (t == NB - 1) g_rowptr[NN] = excl + v;
}

__global__ __launch_bounds__(256) void k_scanC() {
    int i = blockIdx.x * 256 + threadIdx.x;
    int lane = threadIdx.x & 31, wid = threadIdx.x >> 5;
    __shared__ int sw[8];
    int v = (i < NN) ? g_deg[i] : 0;
    int incl = v;
    #pragma unroll
    for (int o = 1; o < 32; o <<= 1) {
        int n = __shfl_up_sync(0xffffffffu, incl, o);
        if (lane >= o) incl += n;
    }
    if (lane == 31) sw[wid] = incl;
    __syncthreads();
    if (threadIdx.x == 0) {
        int run = 0;
        #pragma unroll
        for (int j = 0; j < 8; j++) { int x = sw[j]; sw[j] = run; run += x; }
    }
    __syncthreads();
    int excl = g_boff[blockIdx.x] + sw[wid] + incl - v;
    if (i < NN) {
        g_rowptr[i] = excl;
        g_cursor[i] = excl;
        g_dinv[i]   = rsqrtf((float)(v + 1));   // +1 self loop
    }
}

// ---------------- CSR scatter: pack {src, dinv[src]} (2 edges / thread) ------
__global__ void k_scatter(const void* __restrict__ eidx) {
    int i = blockIdx.x * blockDim.x + threadIdx.x;   // pair index
    if (i * 2 >= EP) return;
    int r0, r1, c0, c1;
    if (g_is64) {
        const long long* e64 = (const long long*)eidx;
        longlong2 vr = ((const longlong2*)e64)[i];
        longlong2 vc = ((const longlong2*)(e64 + EP))[i];
        r0 = (int)vr.x; r1 = (int)vr.y;
        c0 = (int)vc.x; c1 = (int)vc.y;
    } else {
        const int* e32 = (const int*)eidx;
        int2 vr = ((const int2*)e32)[i];
        int2 vc = ((const int2*)(e32 + EP))[i];
        r0 = vr.x; r1 = vr.y;
        c0 = vc.x; c1 = vc.y;
    }
    float d0 = g_dinv[r0], d1 = g_dinv[r1];
    int p0 = atomicAdd(&g_cursor[c0], 1);
    g_edge[p0] = make_uint2((unsigned)r0, __float_as_uint(d0));
    int p1 = atomicAdd(&g_cursor[c1], 1);
    g_edge[p1] = make_uint2((unsigned)r1, __float_as_uint(d1));
}

// ---------------- GEMM1 (W in SMEM) ------------------------------------------
__global__ __launch_bounds__(256) void k_gemm1(const float* __restrict__ x,
                                               const float* __restrict__ W) {
    __shared__ float Ws[FIN * FH];
    int tx = threadIdx.x, ty = threadIdx.y;       // (8, 32)
    int tid = ty * 8 + tx;
    for (int i = tid; i < FIN * FH; i += 256) Ws[i] = W[i];
    __syncthreads();
    int row = blockIdx.x * 32 + ty;
    const float4* x4 = (const float4*)(x + (size_t)row * FIN);
    float acc[8];
    #pragma unroll
    for (int j = 0; j < 8; j++) acc[j] = 0.f;
    int cb = tx * 8;
    #pragma unroll 4
    for (int k4 = 0; k4 < FIN / 4; k4++) {
        float4 xv = x4[k4];
        const float* w = &Ws[(k4 * 4) * FH + cb];
        #pragma unroll
        for (int j = 0; j < 8; j++) acc[j] = fmaf(xv.x, w[j],          acc[j]);
        #pragma unroll
        for (int j = 0; j < 8; j++) acc[j] = fmaf(xv.y, w[FH + j],     acc[j]);
        #pragma unroll
        for (int j = 0; j < 8; j++) acc[j] = fmaf(xv.z, w[2 * FH + j], acc[j]);
        #pragma unroll
        for (int j = 0; j < 8; j++) acc[j] = fmaf(xv.w, w[3 * FH + j], acc[j]);
    }
    float* o = &g_xw[(size_t)row * FH + cb];
    #pragma unroll
    for (int j = 0; j < 8; j++) o[j] = acc[j];
}

// ---------------- agg1 fused with GEMM2 (warp per node) ----------------------
// h(w) = relu(dinv[w]*(xw[w]*dinv[w] + sum xw[src]*dinv[src]) + b1)
// hw(w) = h(w) @ W2   (computed in-register via shuffle broadcast)
__global__ __launch_bounds__(256) void k_agg1f(const float* __restrict__ b1,
                                               const float* __restrict__ W2) {
    __shared__ float Ws[FH * FO];                 // 8 KB
    int tid = threadIdx.x;
    for (int i = tid; i < FH * FO; i += 256) Ws[i] = W2[i];
    __syncthreads();
    int w = (blockIdx.x * 256 + tid) >> 5;
    if (w >= NN) return;
    int lane = tid & 31;
    float dw = g_dinv[w];
    const float* base = &g_xw[(size_t)w * FH];
    float a0 = base[lane] * dw, a1 = base[lane + 32] * dw;  // self loop
    int s = g_rowptr[w], e = g_rowptr[w + 1];
    int p = s;
    for (; p + 4 <= e; p += 4) {
        uint2 e0 = g_edge[p],     e1 = g_edge[p + 1];
        uint2 e2 = g_edge[p + 2], e3 = g_edge[p + 3];
        const float* r0 = &g_xw[(size_t)e0.x * FH];
        const float* r1 = &g_xw[(size_t)e1.x * FH];
        const float* r2 = &g_xw[(size_t)e2.x * FH];
        const float* r3 = &g_xw[(size_t)e3.x * FH];
        float v00 = r0[lane], v01 = r0[lane + 32];
        float v10 = r1[lane], v11 = r1[lane + 32];
        float v20 = r2[lane], v21 = r2[lane + 32];
        float v30 = r3[lane], v31 = r3[lane + 32];
        float d0 = __uint_as_float(e0.y), d1 = __uint_as_float(e1.y);
        float d2 = __uint_as_float(e2.y), d3 = __uint_as_float(e3.y);
        a0 = fmaf(v00, d0, a0); a1 = fmaf(v01, d0, a1);
        a0 = fmaf(v10, d1, a0); a1 = fmaf(v11, d1, a1);
        a0 = fmaf(v20, d2, a0); a1 = fmaf(v21, d2, a1);
        a0 = fmaf(v30, d3, a0); a1 = fmaf(v31, d3, a1);
    }
    for (; p < e; p++) {
        uint2 e0 = g_edge[p];
        float d0 = __uint_as_float(e0.y);
        a0 = fmaf(g_xw[(size_t)e0.x * FH + lane],      d0, a0);
        a1 = fmaf(g_xw[(size_t)e0.x * FH + lane + 32], d0, a1);
    }
    float h0 = fmaxf(fmaf(a0, dw, b1[lane]),      0.f);
    float h1 = fmaxf(fmaf(a1, dw, b1[lane + 32]), 0.f);
    // hw[lane] = sum_k h[k] * W2[k][lane], h distributed across lanes
    float acc = 0.f;
    #pragma unroll
    for (int k = 0; k < 32; k++) {
        float hk0 = __shfl_sync(0xffffffffu, h0, k);
        float hk1 = __shfl_sync(0xffffffffu, h1, k);
        acc = fmaf(hk0, Ws[k * FO + lane],        acc);
        acc = fmaf(hk1, Ws[(k + 32) * FO + lane], acc);
    }
    g_hw[(size_t)w * FO + lane] = acc;
}

__global__ __launch_bounds__(256) void k_agg2(const float* __restrict__ b) {
    int w = (blockIdx.x * 256 + threadIdx.x) >> 5;
    if (w >= NN) return;
    int lane = threadIdx.x & 31;
    float dw = g_dinv[w];
    float a0 = g_hw[(size_t)w * FO + lane] * dw;    // self loop
    int s = g_rowptr[w], e = g_rowptr[w + 1];
    int p = s;
    for (; p + 4 <= e; p += 4) {
        uint2 e0 = g_edge[p],     e1 = g_edge[p + 1];
        uint2 e2 = g_edge[p + 2], e3 = g_edge[p + 3];
        float v0 = g_hw[(size_t)e0.x * FO + lane];
        float v1 = g_hw[(size_t)e1.x * FO + lane];
        float v2 = g_hw[(size_t)e2.x * FO + lane];
        float v3 = g_hw[(size_t)e3.x * FO + lane];
        a0 = fmaf(v0, __uint_as_float(e0.y), a0);
        a0 = fmaf(v1, __uint_as_float(e1.y), a0);
        a0 = fmaf(v2, __uint_as_float(e2.y), a0);
        a0 = fmaf(v3, __uint_as_float(e3.y), a0);
    }
    for (; p < e; p++) {
        uint2 e0 = g_edge[p];
        a0 = fmaf(g_hw[(size_t)e0.x * FO + lane], __uint_as_float(e0.y), a0);
    }
    g_z[(size_t)w * FO + lane] = fmaf(a0, dw, b[lane]);
}

// ---------------- decode: 16 edges/warp, 4 per 8-lane subgroup ---------------
__global__ __launch_bounds__(256) void k_decode(const void* __restrict__ pos,
                                                const void* __restrict__ neg,
                                                float* __restrict__ out) {
    int warp = (blockIdx.x * 256 + threadIdx.x) >> 5;
    int lane = threadIdx.x & 31;
    int sub = lane >> 3, l8 = lane & 7;
    size_t base = (size_t)warp * 16 + sub * 4;       // EP%4==0: pack one-sided
    int is64 = g_is64;
    const void* buf; size_t off;
    if (base < EP) { buf = pos; off = base; }
    else           { buf = neg; off = base - EP; }
    int a[4], c[4];
    #pragma unroll
    for (int t = 0; t < 4; t++) {
        a[t] = edge_at(buf, is64, off + t);
        c[t] = edge_at(buf, is64, (size_t)EP + off + t);
    }
    float4 va[4], vb[4];
    #pragma unroll
    for (int t = 0; t < 4; t++) {
        va[t] = ((const float4*)(g_z + (size_t)a[t] * FO))[l8];
        vb[t] = ((const float4*)(g_z + (size_t)c[t] * FO))[l8];
    }
    float v[4];
    #pragma unroll
    for (int t = 0; t < 4; t++)
        v[t] = va[t].x * vb[t].x + va[t].y * vb[t].y
             + va[t].z * vb[t].z + va[t].w * vb[t].w;
    #pragma unroll
    for (int o = 4; o; o >>= 1) {
        #pragma unroll
        for (int t = 0; t < 4; t++) v[t] += __shfl_xor_sync(0xffffffffu, v[t], o);
    }
    if (l8 == 0)
        ((float4*)out)[base >> 2] = make_float4(v[0], v[1], v[2], v[3]);
}

// edge_index echoed as floats if the harness output includes it
__global__ void k_tail(const void* __restrict__ pos,
                       const void* __restrict__ neg,
                       float* __restrict__ out, int count) {
    int i = blockIdx.x * blockDim.x + threadIdx.x;
    if (i >= count) return;
    int is64 = g_is64;
    int r = i / ET, c = i % ET;
    int v = (c < EP) ? edge_at(pos, is64, (size_t)r * EP + c)
                     : edge_at(neg, is64, (size_t)r * EP + (c - EP));
    out[ET + i] = (float)v;
}

// ---------------- launcher ---------------------------------------------------
extern "C" void kernel_launch(void* const* d_in, const int* in_sizes, int n_in,
                              void* d_out, int out_size) {
    // created on the first (uncaptured) correctness call; reused under capture
    static cudaStream_t s2 = 0;
    static cudaEvent_t evFork = 0, evJoin = 0, evTail = 0;
    if (!s2) {
        cudaStreamCreateWithFlags(&s2, cudaStreamNonBlocking);
        cudaEventCreateWithFlags(&evFork, cudaEventDisableTiming);
        cudaEventCreateWithFlags(&evJoin, cudaEventDisableTiming);
        cudaEventCreateWithFlags(&evTail, cudaEventDisableTiming);
    }

    const float *x = 0, *W1 = 0, *b1 = 0, *W2 = 0, *b2 = 0;
    const void *pos = 0, *neg = 0;
    for (int i = 0; i < n_in; i++) {
        switch (in_sizes[i]) {
            case NN * FIN:  x  = (const float*)d_in[i]; break;
            case FIN * FH:  W1 = (const float*)d_in[i]; break;
            case FH:        b1 = (const float*)d_in[i]; break;
            case FH * FO:   W2 = (const float*)d_in[i]; break;
            case FO:        b2 = (const float*)d_in[i]; break;
            case 2 * EP:
                if (!pos) pos = d_in[i];
                else      neg = d_in[i];
                break;
            default: break;
        }
    }
    float* out = (float*)d_out;

    // fork: GEMM1 + edge echo (independent of graph preprocessing) on s2
    cudaEventRecord(evFork, 0);
    cudaStreamWaitEvent(s2, evFork, 0);
    k_gemm1<<<NN / 32, dim3(8, 32), 0, s2>>>(x, W1);
    cudaEventRecord(evJoin, s2);
    int cnt = 0;
    if (out_size > ET) {
        cnt = out_size - ET;
        if (cnt > 2 * ET) cnt = 2 * ET;
        k_tail<<<(cnt + 255) / 256, 256, 0, s2>>>(pos, neg, out, cnt);
        cudaEventRecord(evTail, s2);
    }

    // preprocessing chain on main stream
    k_init   <<<(NN + 255) / 256, 256>>>((const int*)pos);
    k_hist   <<<(EP / 2 + 255) / 256, 256>>>(pos);
    k_scanA  <<<NB, 256>>>();
    k_scanB  <<<1, 512>>>();
    k_scanC  <<<NB, 256>>>();
    k_scatter<<<(EP / 2 + 255) / 256, 256>>>(pos);

    // join gemm1, then fused layer pipeline
    cudaStreamWaitEvent(0, evJoin, 0);
    k_agg1f<<<(NN * 32 + 255) / 256, 256>>>(b1, W2);
    k_agg2 <<<(NN * 32 + 255) / 256, 256>>>(b2);

    if (cnt) cudaStreamWaitEvent(0, evTail, 0);
    // decode: 16 edges per warp; grid exact (ET % 16 == 0)
    k_decode<<<(ET / 16) * 32 / 256, 256>>>(pos, neg, out);
}

// round 7
// speedup vs baseline: 2.8418x; 1.5697x over previous
#include <cuda_runtime.h>
#include <cstdint>

#define NN  100000
#define EP  1600000
#define ET  3200000
#define FIN 128
#define FH  64
#define FO  32
#define NB  ((NN + 255) / 256)   // 391 scan blocks

// ---------------- scratch (static device globals; no allocation) ------------
__device__ int   g_is64;
__device__ int   g_deg[NN];
__device__ int   g_bsum[512];
__device__ int   g_boff[512];
__device__ int   g_rowptr[NN + 1];
__device__ int   g_cursor[NN];
__device__ uint2 g_edge[EP];              // {src, __float_as_uint(dinv[src])}
__device__ float g_dinv[NN];
__device__ float g_xw[(size_t)NN * FH];   // layer1 linear out (unscaled)
__device__ float g_hw[(size_t)NN * FO];   // layer2 linear out (unscaled)
__device__ float g_z [(size_t)NN * FO];   // layer2 embedding

__device__ __forceinline__ int edge_at(const void* p, int is64, size_t idx) {
    if (is64) return (int)((const long long*)p)[idx];
    return ((const int*)p)[idx];
}

// ---------------- init: zero degrees + dtype probe ---------------------------
__global__ void k_init(const int* __restrict__ p) {
    int i = blockIdx.x * blockDim.x + threadIdx.x;
    if (i < NN) g_deg[i] = 0;
    if (blockIdx.x == 0) {
        __shared__ int nz;
        if (threadIdx.x == 0) nz = 0;
        __syncthreads();
        if (threadIdx.x < 256 && p[threadIdx.x * 2 + 1] != 0) atomicAdd(&nz, 1);
        __syncthreads();
        if (threadIdx.x == 0) g_is64 = (nz == 0) ? 1 : 0;
    }
}

// ---------------- degree histogram (2 edges / thread) ------------------------
__global__ void k_hist(const void* __restrict__ eidx) {
    int i = blockIdx.x * blockDim.x + threadIdx.x;
    if (i * 2 >= EP) return;
    int c0, c1;
    if (g_is64) {
        longlong2 v = ((const longlong2*)((const long long*)eidx + EP))[i];
        c0 = (int)v.x; c1 = (int)v.y;
    } else {
        int2 v = ((const int2*)((const int*)eidx + EP))[i];
        c0 = v.x; c1 = v.y;
    }
    atomicAdd(&g_deg[c0], 1);
    atomicAdd(&g_deg[c1], 1);
}

// ---------------- 3-phase parallel scan --------------------------------------
__global__ __launch_bounds__(256) void k_scanA() {
    int i = blockIdx.x * 256 + threadIdx.x;
    int lane = threadIdx.x & 31, wid = threadIdx.x >> 5;
    __shared__ int sw[8];
    int v = (i < NN) ? g_deg[i] : 0;
    #pragma unroll
    for (int o = 16; o; o >>= 1) v += __shfl_xor_sync(0xffffffffu, v, o);
    if (lane == 0) sw[wid] = v;
    __syncthreads();
    if (threadIdx.x == 0) {
        int t = 0;
        #pragma unroll
        for (int j = 0; j < 8; j++) t += sw[j];
        g_bsum[blockIdx.x] = t;
    }
}

__global__ void k_scanB() {
    __shared__ int sm[16];
    int t = threadIdx.x, lane = t & 31, wid = t >> 5;
    int v = (t < NB) ? g_bsum[t] : 0;
    int incl = v;
    #pragma unroll
    for (int o = 1; o < 32; o <<= 1) {
        int n = __shfl_up_sync(0xffffffffu, incl, o);
        if (lane >= o) incl += n;
    }
    if (lane == 31) sm[wid] = incl;
    __syncthreads();
    if (t == 0) {
        int run = 0;
        #pragma unroll
        for (int j = 0; j < 16; j++) { int x = sm[j]; sm[j] = run; run += x; }
    }
    __syncthreads();
    int excl = sm[wid] + incl - v;
    if (t < NB) g_boff[t] = excl;
    if (t == NB - 1) g_rowptr[NN] = excl + v;
}

__global__ __launch_bounds__(256) void k_scanC() {
    int i = blockIdx.x * 256 + threadIdx.x;
    int lane = threadIdx.x & 31, wid = threadIdx.x >> 5;
    __shared__ int sw[8];
    int v = (i < NN) ? g_deg[i] : 0;
    int incl = v;
    #pragma unroll
    for (int o = 1; o < 32; o <<= 1) {
        int n = __shfl_up_sync(0xffffffffu, incl, o);
        if (lane >= o) incl += n;
    }
    if (lane == 31) sw[wid] = incl;
    __syncthreads();
    if (threadIdx.x == 0) {
        int run = 0;
        #pragma unroll
        for (int j = 0; j < 8; j++) { int x = sw[j]; sw[j] = run; run += x; }
    }
    __syncthreads();
    int excl = g_boff[blockIdx.x] + sw[wid] + incl - v;
    if (i < NN) {
        g_rowptr[i] = excl;
        g_cursor[i] = excl;
        g_dinv[i]   = rsqrtf((float)(v + 1));
    }
}

// ---------------- CSR scatter: pack {src, dinv[src]} ------------------------
__global__ void k_scatter(const void* __restrict__ eidx) {
    int i = blockIdx.x * blockDim.x + threadIdx.x;
    if (i * 2 >= EP) return;
    int r0, r1, c0, c1;
    if (g_is64) {
        const long long* e64 = (const long long*)eidx;
        longlong2 vr = ((const longlong2*)e64)[i];
        longlong2 vc = ((const longlong2*)(e64 + EP))[i];
        r0 = (int)vr.x; r1 = (int)vr.y;
        c0 = (int)vc.x; c1 = (int)vc.y;
    } else {
        const int* e32 = (const int*)eidx;
        int2 vr = ((const int2*)e32)[i];
        int2 vc = ((const int2*)(e32 + EP))[i];
        r0 = vr.x; r1 = vr.y;
        c0 = vc.x; c1 = vc.y;
    }
    float d0 = g_dinv[r0], d1 = g_dinv[r1];
    int p0 = atomicAdd(&g_cursor[c0], 1);
    g_edge[p0] = make_uint2((unsigned)r0, __float_as_uint(d0));
    int p1 = atomicAdd(&g_cursor[c1], 1);
    g_edge[p1] = make_uint2((unsigned)r1, __float_as_uint(d1));
}

// ---------------- GEMM1: 4 rows x 8 cols per thread (LDS /4) -----------------
__global__ __launch_bounds__(256) void k_gemm1(const float* __restrict__ x,
                                               const float* __restrict__ W) {
    __shared__ float Ws[FIN * FH];                // 32 KB
    int tx = threadIdx.x, ty = threadIdx.y;       // (8, 32)
    int tid = ty * 8 + tx;
    {
        const float4* W4 = (const float4*)W;
        float4* Ws4 = (float4*)Ws;
        for (int i = tid; i < FIN * FH / 4; i += 256) Ws4[i] = W4[i];
    }
    __syncthreads();
    int rbase = blockIdx.x * 128 + ty;            // rows: rbase + {0,32,64,96}
    int cb = tx * 8;
    const float4* x0 = (const float4*)(x + (size_t)(rbase)      * FIN);
    const float4* x1 = (const float4*)(x + (size_t)(rbase + 32) * FIN);
    const float4* x2 = (const float4*)(x + (size_t)(rbase + 64) * FIN);
    const float4* x3 = (const float4*)(x + (size_t)(rbase + 96) * FIN);
    bool v0 = rbase      < NN, v1 = rbase + 32 < NN;
    bool v2 = rbase + 64 < NN, v3 = rbase + 96 < NN;
    float acc[4][8];
    #pragma unroll
    for (int i = 0; i < 4; i++)
        #pragma unroll
        for (int j = 0; j < 8; j++) acc[i][j] = 0.f;
    #pragma unroll 2
    for (int k4 = 0; k4 < FIN / 4; k4++) {
        float4 xv[4];
        xv[0] = v0 ? x0[k4] : make_float4(0, 0, 0, 0);
        xv[1] = v1 ? x1[k4] : make_float4(0, 0, 0, 0);
        xv[2] = v2 ? x2[k4] : make_float4(0, 0, 0, 0);
        xv[3] = v3 ? x3[k4] : make_float4(0, 0, 0, 0);
        const float* w = &Ws[(k4 * 4) * FH + cb];
        #pragma unroll
        for (int kk = 0; kk < 4; kk++) {
            const float* wk = w + kk * FH;
            #pragma unroll
            for (int j = 0; j < 8; j++) {
                float wv = wk[j];
                acc[0][j] = fmaf(((const float*)&xv[0])[kk], wv, acc[0][j]);
                acc[1][j] = fmaf(((const float*)&xv[1])[kk], wv, acc[1][j]);
                acc[2][j] = fmaf(((const float*)&xv[2])[kk], wv, acc[2][j]);
                acc[3][j] = fmaf(((const float*)&xv[3])[kk], wv, acc[3][j]);
            }
        }
    }
    #pragma unroll
    for (int i = 0; i < 4; i++) {
        int r = rbase + i * 32;
        if (r < NN) {
            float* o = &g_xw[(size_t)r * FH + cb];
            #pragma unroll
            for (int j = 0; j < 8; j++) o[j] = acc[i][j];
        }
    }
}

// ---------------- agg1 fused with GEMM2: float4 rows, 2 edges/step ----------
__global__ __launch_bounds__(256) void k_agg1f(const float* __restrict__ b1,
                                               const float* __restrict__ W2) {
    __shared__ float Ws[FH * FO];                 // 8 KB
    int tid = threadIdx.x;
    {
        const float4* W4 = (const float4*)W2;
        float4* Ws4 = (float4*)Ws;
        for (int i = tid; i < FH * FO / 4; i += 256) Ws4[i] = W4[i];
    }
    __syncthreads();
    int w = (blockIdx.x * 256 + tid) >> 5;
    if (w >= NN) return;
    int lane = tid & 31;
    int half = lane >> 4, q = lane & 15;          // q indexes 16B chunks of row
    float dw = g_dinv[w];
    float4 acc = make_float4(0, 0, 0, 0);
    if (half == 0) {                              // self loop on half 0
        float4 sv = ((const float4*)(g_xw + (size_t)w * FH))[q];
        acc.x = sv.x * dw; acc.y = sv.y * dw; acc.z = sv.z * dw; acc.w = sv.w * dw;
    }
    int s = g_rowptr[w], e = g_rowptr[w + 1];
    int p = s;
    for (; p + 8 <= e; p += 8) {                  // 4 pair-steps, 8 edges
        uint2 r0 = g_edge[p     + half];
        uint2 r1 = g_edge[p + 2 + half];
        uint2 r2 = g_edge[p + 4 + half];
        uint2 r3 = g_edge[p + 6 + half];
        float4 u0 = ((const float4*)(g_xw + (size_t)r0.x * FH))[q];
        float4 u1 = ((const float4*)(g_xw + (size_t)r1.x * FH))[q];
        float4 u2 = ((const float4*)(g_xw + (size_t)r2.x * FH))[q];
        float4 u3 = ((const float4*)(g_xw + (size_t)r3.x * FH))[q];
        float d0 = __uint_as_float(r0.y), d1 = __uint_as_float(r1.y);
        float d2 = __uint_as_float(r2.y), d3 = __uint_as_float(r3.y);
        acc.x = fmaf(u0.x, d0, acc.x); acc.y = fmaf(u0.y, d0, acc.y);
        acc.z = fmaf(u0.z, d0, acc.z); acc.w = fmaf(u0.w, d0, acc.w);
        acc.x = fmaf(u1.x, d1, acc.x); acc.y = fmaf(u1.y, d1, acc.y);
        acc.z = fmaf(u1.z, d1, acc.z); acc.w = fmaf(u1.w, d1, acc.w);
        acc.x = fmaf(u2.x, d2, acc.x); acc.y = fmaf(u2.y, d2, acc.y);
        acc.z = fmaf(u2.z, d2, acc.z); acc.w = fmaf(u2.w, d2, acc.w);
        acc.x = fmaf(u3.x, d3, acc.x); acc.y = fmaf(u3.y, d3, acc.y);
        acc.z = fmaf(u3.z, d3, acc.z); acc.w = fmaf(u3.w, d3, acc.w);
    }
    for (; p + 2 <= e; p += 2) {                  // pair remainder
        uint2 r0 = g_edge[p + half];
        float4 u0 = ((const float4*)(g_xw + (size_t)r0.x * FH))[q];
        float d0 = __uint_as_float(r0.y);
        acc.x = fmaf(u0.x, d0, acc.x); acc.y = fmaf(u0.y, d0, acc.y);
        acc.z = fmaf(u0.z, d0, acc.z); acc.w = fmaf(u0.w, d0, acc.w);
    }
    if (p < e) {                                  // odd edge: half 0 only
        uint2 r0 = g_edge[p + (half ? 0 : 0)];    // same record, d=0 on half 1
        float4 u0 = ((const float4*)(g_xw + (size_t)r0.x * FH))[q];
        float d0 = half ? 0.f : __uint_as_float(r0.y);
        acc.x = fmaf(u0.x, d0, acc.x); acc.y = fmaf(u0.y, d0, acc.y);
        acc.z = fmaf(u0.z, d0, acc.z); acc.w = fmaf(u0.w, d0, acc.w);
    }
    // combine halves: all lanes end with the full sum for features q*4..q*4+3
    acc.x += __shfl_xor_sync(0xffffffffu, acc.x, 16);
    acc.y += __shfl_xor_sync(0xffffffffu, acc.y, 16);
    acc.z += __shfl_xor_sync(0xffffffffu, acc.z, 16);
    acc.w += __shfl_xor_sync(0xffffffffu, acc.w, 16);
    float4 bias = ((const float4*)b1)[q];
    float4 h;
    h.x = fmaxf(fmaf(acc.x, dw, bias.x), 0.f);
    h.y = fmaxf(fmaf(acc.y, dw, bias.y), 0.f);
    h.z = fmaxf(fmaf(acc.z, dw, bias.z), 0.f);
    h.w = fmaxf(fmaf(acc.w, dw, bias.w), 0.f);
    // GEMM2 epilogue: hw[c] = sum_f h[f] * W2[f][c]; h[f] at lane f>>2
    float o = 0.f;
    #pragma unroll
    for (int f4 = 0; f4 < 16; f4++) {
        float h0 = __shfl_sync(0xffffffffu, h.x, f4);
        float h1 = __shfl_sync(0xffffffffu, h.y, f4);
        float h2 = __shfl_sync(0xffffffffu, h.z, f4);
        float h3 = __shfl_sync(0xffffffffu, h.w, f4);
        o = fmaf(h0, Ws[(f4 * 4 + 0) * FO + lane], o);
        o = fmaf(h1, Ws[(f4 * 4 + 1) * FO + lane], o);
        o = fmaf(h2, Ws[(f4 * 4 + 2) * FO + lane], o);
        o = fmaf(h3, Ws[(f4 * 4 + 3) * FO + lane], o);
    }
    g_hw[(size_t)w * FO + lane] = o;
}

// ---------------- agg2: float4 rows, 4 edges/step ----------------------------
__global__ __launch_bounds__(256) void k_agg2(const float* __restrict__ b) {
    int w = (blockIdx.x * 256 + threadIdx.x) >> 5;
    if (w >= NN) return;
    int lane = threadIdx.x & 31;
    int g = lane >> 3, l8 = lane & 7;             // l8 indexes 16B chunks (128B row)
    float dw = g_dinv[w];
    float4 acc = make_float4(0, 0, 0, 0);
    if (g == 0) {                                 // self loop on group 0
        float4 sv = ((const float4*)(g_hw + (size_t)w * FO))[l8];
        acc.x = sv.x * dw; acc.y = sv.y * dw; acc.z = sv.z * dw; acc.w = sv.w * dw;
    }
    int s = g_rowptr[w], e = g_rowptr[w + 1];
    int p = s;
    for (; p + 8 <= e; p += 8) {                  // 2 quad-steps, 8 edges
        uint2 r0 = g_edge[p     + g];
        uint2 r1 = g_edge[p + 4 + g];
        float4 u0 = ((const float4*)(g_hw + (size_t)r0.x * FO))[l8];
        float4 u1 = ((const float4*)(g_hw + (size_t)r1.x * FO))[l8];
        float d0 = __uint_as_float(r0.y), d1 = __uint_as_float(r1.y);
        acc.x = fmaf(u0.x, d0, acc.x); acc.y = fmaf(u0.y, d0, acc.y);
        acc.z = fmaf(u0.z, d0, acc.z); acc.w = fmaf(u0.w, d0, acc.w);
        acc.x = fmaf(u1.x, d1, acc.x); acc.y = fmaf(u1.y, d1, acc.y);
        acc.z = fmaf(u1.z, d1, acc.z); acc.w = fmaf(u1.w, d1, acc.w);
    }
    for (; p + 4 <= e; p += 4) {
        uint2 r0 = g_edge[p + g];
        float4 u0 = ((const float4*)(g_hw + (size_t)r0.x * FO))[l8];
        float d0 = __uint_as_float(r0.y);
        acc.x = fmaf(u0.x, d0, acc.x); acc.y = fmaf(u0.y, d0, acc.y);
        acc.z = fmaf(u0.z, d0, acc.z); acc.w = fmaf(u0.w, d0, acc.w);
    }
    if (p < e) {                                  // remainder 1..3 edges
        int rem = e - p;
        uint2 r0 = g_edge[p + (g < rem ? g : 0)];
        float4 u0 = ((const float4*)(g_hw + (size_t)r0.x * FO))[l8];
        float d0 = (g < rem) ? __uint_as_float(r0.y) : 0.f;
        acc.x = fmaf(u0.x, d0, acc.x); acc.y = fmaf(u0.y, d0, acc.y);
        acc.z = fmaf(u0.z, d0, acc.z); acc.w = fmaf(u0.w, d0, acc.w);
    }
    // combine 4 groups
    #pragma unroll
    for (int o = 8; o <= 16; o <<= 1) {
        acc.x += __shfl_xor_sync(0xffffffffu, acc.x, o);
        acc.y += __shfl_xor_sync(0xffffffffu, acc.y, o);
        acc.z += __shfl_xor_sync(0xffffffffu, acc.z, o);
        acc.w += __shfl_xor_sync(0xffffffffu, acc.w, o);
    }
    if (g == 0) {
        float4 bias = ((const float4*)b)[l8];
        float4 z;
        z.x = fmaf(acc.x, dw, bias.x);
        z.y = fmaf(acc.y, dw, bias.y);
        z.z = fmaf(acc.z, dw, bias.z);
        z.w = fmaf(acc.w, dw, bias.w);
        ((float4*)(g_z + (size_t)w * FO))[l8] = z;
    }
}

// ---------------- decode: 16 edges/warp, 4 per 8-lane subgroup ---------------
__global__ __launch_bounds__(256) void k_decode(const void* __restrict__ pos,
                                                const void* __restrict__ neg,
                                                float* __restrict__ out) {
    int warp = (blockIdx.x * 256 + threadIdx.x) >> 5;
    int lane = threadIdx.x & 31;
    int sub = lane >> 3, l8 = lane & 7;
    size_t base = (size_t)warp * 16 + sub * 4;
    int is64 = g_is64;
    const void* buf; size_t off;
    if (base < EP) { buf = pos; off = base; }
    else           { buf = neg; off = base - EP; }
    int a[4], c[4];
    #pragma unroll
    for (int t = 0; t < 4; t++) {
        a[t] = edge_at(buf, is64, off + t);
        c[t] = edge_at(buf, is64, (size_t)EP + off + t);
    }
    float4 va[4], vb[4];
    #pragma unroll
    for (int t = 0; t < 4; t++) {
        va[t] = ((const float4*)(g_z + (size_t)a[t] * FO))[l8];
        vb[t] = ((const float4*)(g_z + (size_t)c[t] * FO))[l8];
    }
    float v[4];
    #pragma unroll
    for (int t = 0; t < 4; t++)
        v[t] = va[t].x * vb[t].x + va[t].y * vb[t].y
             + va[t].z * vb[t].z + va[t].w * vb[t].w;
    #pragma unroll
    for (int o = 4; o; o >>= 1) {
        #pragma unroll
        for (int t = 0; t < 4; t++) v[t] += __shfl_xor_sync(0xffffffffu, v[t], o);
    }
    if (l8 == 0)
        ((float4*)out)[base >> 2] = make_float4(v[0], v[1], v[2], v[3]);
}

// edge_index echoed as floats if the harness output includes it
__global__ void k_tail(const void* __restrict__ pos,
                       const void* __restrict__ neg,
                       float* __restrict__ out, int count) {
    int i = blockIdx.x * blockDim.x + threadIdx.x;
    if (i >= count) return;
    int is64 = g_is64;
    int r = i / ET, c = i % ET;
    int v = (c < EP) ? edge_at(pos, is64, (size_t)r * EP + c)
                     : edge_at(neg, is64, (size_t)r * EP + (c - EP));
    out[ET + i] = (float)v;
}

// ---------------- launcher ---------------------------------------------------
extern "C" void kernel_launch(void* const* d_in, const int* in_sizes, int n_in,
                              void* d_out, int out_size) {
    static cudaStream_t s2 = 0;
    static cudaEvent_t evFork = 0, evJoin = 0, evTail = 0;
    if (!s2) {
        cudaStreamCreateWithFlags(&s2, cudaStreamNonBlocking);
        cudaEventCreateWithFlags(&evFork, cudaEventDisableTiming);
        cudaEventCreateWithFlags(&evJoin, cudaEventDisableTiming);
        cudaEventCreateWithFlags(&evTail, cudaEventDisableTiming);
    }

    const float *x = 0, *W1 = 0, *b1 = 0, *W2 = 0, *b2 = 0;
    const void *pos = 0, *neg = 0;
    for (int i = 0; i < n_in; i++) {
        switch (in_sizes[i]) {
            case NN * FIN:  x  = (const float*)d_in[i]; break;
            case FIN * FH:  W1 = (const float*)d_in[i]; break;
            case FH:        b1 = (const float*)d_in[i]; break;
            case FH * FO:   W2 = (const float*)d_in[i]; break;
            case FO:        b2 = (const float*)d_in[i]; break;
            case 2 * EP:
                if (!pos) pos = d_in[i];
                else      neg = d_in[i];
                break;
            default: break;
        }
    }
    float* out = (float*)d_out;

    // fork: GEMM1 + edge echo (independent of graph preprocessing) on s2
    cudaEventRecord(evFork, 0);
    cudaStreamWaitEvent(s2, evFork, 0);
    k_gemm1<<<(NN + 127) / 128, dim3(8, 32), 0, s2>>>(x, W1);
    cudaEventRecord(evJoin, s2);
    int cnt = 0;
    if (out_size > ET) {
        cnt = out_size - ET;
        if (cnt > 2 * ET) cnt = 2 * ET;
        k_tail<<<(cnt + 255) / 256, 256, 0, s2>>>(pos, neg, out, cnt);
        cudaEventRecord(evTail, s2);
    }

    // preprocessing chain on main stream
    k_init   <<<(NN + 255) / 256, 256>>>((const int*)pos);
    k_hist   <<<(EP / 2 + 255) / 256, 256>>>(pos);
    k_scanA  <<<NB, 256>>>();
    k_scanB  <<<1, 512>>>();
    k_scanC  <<<NB, 256>>>();
    k_scatter<<<(EP / 2 + 255) / 256, 256>>>(pos);

    // join gemm1, then fused layer pipeline
    cudaStreamWaitEvent(0, evJoin, 0);
    k_agg1f<<<(NN * 32 + 255) / 256, 256>>>(b1, W2);
    k_agg2 <<<(NN * 32 + 255) / 256, 256>>>(b2);

    if (cnt) cudaStreamWaitEvent(0, evTail, 0);
    k_decode<<<(ET / 16) * 32 / 256, 256>>>(pos, neg, out);
}